// round 3
// baseline (speedup 1.0000x reference)
#include <cuda_runtime.h>
#include <cuda_bf16.h>

// Problem constants
#define B    32
#define LQ   32
#define DLEN 4096
#define P    16
#define D    2048
#define H    2048

#define KSPLIT 16           // k-split for skinny GEMMs
#define TILE_N 64
#define KB     64
#define NQ     4            // quarters per passage in psum

// ---------------- scratch (device globals; no allocation allowed) ----------------
__device__ float g_qrep[B * D];
__device__ float g_qenc[B * H];
__device__ float g_v[B * D];
__device__ float g_part[KSPLIT * B * 2048];      // GEMM partials (4 MB)
__device__ float g_c[B];
__device__ float g_psum[NQ * B * P * D];         // passage embedding sums (16 MB)

// ---------------- q_rep = masked mean of query token embeddings ----------------
__global__ void k_qrep(const int* __restrict__ queries,
                       const int* __restrict__ qlen,
                       const float* __restrict__ emb) {
    int b = blockIdx.x;
    __shared__ int toks[LQ];
    if (threadIdx.x < LQ) toks[threadIdx.x] = queries[b * LQ + threadIdx.x];
    int len = qlen[b];
    __syncthreads();
    float inv = 1.0f / (float)len;
    int d = blockIdx.y * 256 + threadIdx.x;
    float s = 0.0f;
    for (int l = 0; l < len; l++) s += emb[(size_t)toks[l] * D + d];
    g_qrep[b * D + d] = s * inv;
}

// ---------------- skinny GEMM  C[32,2048] = A[32,2048] x W (optionally transposed) ----
__global__ void k_gemm(const float* __restrict__ A,
                       const float* __restrict__ W,
                       int transW) {
    const int n0 = blockIdx.x * TILE_N;
    const int k0 = blockIdx.y * (2048 / KSPLIT);
    __shared__ float As[32][KB];
    __shared__ float Ws[TILE_N][KB + 1];

    const int t  = threadIdx.x;      // 256 threads
    const int tb = t >> 5;
    const int tn = t & 31;

    float acc00 = 0.f, acc01 = 0.f, acc10 = 0.f, acc11 = 0.f;
    float acc20 = 0.f, acc21 = 0.f, acc30 = 0.f, acc31 = 0.f;

    for (int kc = 0; kc < (2048 / KSPLIT); kc += KB) {
        const int kbase = k0 + kc;
        #pragma unroll
        for (int i = 0; i < 8; i++) {
            int flat = t + i * 256;
            int bb = flat >> 6, kk = flat & 63;
            As[bb][kk] = A[bb * 2048 + kbase + kk];
        }
        if (!transW) {
            #pragma unroll
            for (int i = 0; i < 16; i++) {
                int flat = t + i * 256;
                int nn = flat >> 6, kk = flat & 63;
                Ws[nn][kk] = W[(size_t)(n0 + nn) * 2048 + kbase + kk];
            }
        } else {
            #pragma unroll
            for (int i = 0; i < 16; i++) {
                int flat = t + i * 256;
                int nn = flat & 63, kk = flat >> 6;
                Ws[nn][kk] = W[(size_t)(kbase + kk) * 2048 + n0 + nn];
            }
        }
        __syncthreads();

        #pragma unroll 16
        for (int k = 0; k < KB; k++) {
            float a0 = As[tb * 4 + 0][k];
            float a1 = As[tb * 4 + 1][k];
            float a2 = As[tb * 4 + 2][k];
            float a3 = As[tb * 4 + 3][k];
            float w0 = Ws[tn][k];
            float w1 = Ws[tn + 32][k];
            acc00 += a0 * w0; acc01 += a0 * w1;
            acc10 += a1 * w0; acc11 += a1 * w1;
            acc20 += a2 * w0; acc21 += a2 * w1;
            acc30 += a3 * w0; acc31 += a3 * w1;
        }
        __syncthreads();
    }

    float* out = g_part + (size_t)blockIdx.y * 32 * 2048;
    out[(tb * 4 + 0) * 2048 + n0 + tn]      = acc00;
    out[(tb * 4 + 0) * 2048 + n0 + tn + 32] = acc01;
    out[(tb * 4 + 1) * 2048 + n0 + tn]      = acc10;
    out[(tb * 4 + 1) * 2048 + n0 + tn + 32] = acc11;
    out[(tb * 4 + 2) * 2048 + n0 + tn]      = acc20;
    out[(tb * 4 + 2) * 2048 + n0 + tn + 32] = acc21;
    out[(tb * 4 + 3) * 2048 + n0 + tn]      = acc30;
    out[(tb * 4 + 3) * 2048 + n0 + tn + 32] = acc31;
}

// vectorized partial reduce: 16384 float4 elements, 16 independent loads/thread
__global__ void k_reduce(float* __restrict__ C,
                         const float* __restrict__ bias,
                         int addBias) {
    int idx = blockIdx.x * 256 + threadIdx.x;   // over 16384 float4
    const float4* part4 = (const float4*)g_part;
    float4 s = make_float4(0.f, 0.f, 0.f, 0.f);
    #pragma unroll
    for (int sp = 0; sp < KSPLIT; sp++) {
        float4 x = part4[sp * 16384 + idx];
        s.x += x.x; s.y += x.y; s.z += x.z; s.w += x.w;
    }
    if (addBias) {
        float4 bb = ((const float4*)bias)[idx & 511];
        s.x += bb.x; s.y += bb.y; s.z += bb.z; s.w += bb.w;
    }
    ((float4*)C)[idx] = s;
}

// c[b] = q_enc[b] . bias
__global__ void k_qc(const float* __restrict__ bias) {
    int b = blockIdx.x;
    float s = 0.0f;
    for (int i = threadIdx.x; i < H; i += 256) s += g_qenc[b * H + i] * bias[i];
    __shared__ float red[256];
    red[threadIdx.x] = s;
    __syncthreads();
    for (int o = 128; o; o >>= 1) {
        if (threadIdx.x < o) red[threadIdx.x] += red[threadIdx.x + o];
        __syncthreads();
    }
    if (threadIdx.x == 0) g_c[b] = red[0];
}

// ---------------- passage embedding sums: quarter-passages for balance ----------------
// grid (B, P, NQ); block sums its quarter's emb rows into [D] accumulator.
__global__ void k_psum(const int* __restrict__ docs,
                       const int* __restrict__ plen,
                       const float* __restrict__ emb) {
    const int b = blockIdx.x, p = blockIdx.y, h = blockIdx.z;
    const int t = threadIdx.x;

    __shared__ int toks[64];
    __shared__ int info[2];

    if (t == 0) {
        int start = 0;
        for (int q = 0; q < p; q++) start += plen[b * P + q];
        int len = plen[b * P + p];
        int i0 = (len * h) >> 2;
        int i1 = (len * (h + 1)) >> 2;
        info[0] = start + i0;
        info[1] = i1 - i0;
    }
    __syncthreads();
    const int hstart = info[0];
    const int nt = info[1];
    if (t < nt) toks[t] = docs[b * DLEN + hstart + t];
    __syncthreads();

    float4 acc0 = make_float4(0.f, 0.f, 0.f, 0.f);
    float4 acc1 = make_float4(0.f, 0.f, 0.f, 0.f);

    int tk = 0;
    for (; tk + 4 <= nt; tk += 4) {
        const float4* r0 = (const float4*)(emb + (size_t)toks[tk + 0] * D);
        const float4* r1 = (const float4*)(emb + (size_t)toks[tk + 1] * D);
        const float4* r2 = (const float4*)(emb + (size_t)toks[tk + 2] * D);
        const float4* r3 = (const float4*)(emb + (size_t)toks[tk + 3] * D);
        float4 a0 = r0[t], b0 = r0[t + 256];
        float4 a1 = r1[t], b1 = r1[t + 256];
        float4 a2 = r2[t], b2 = r2[t + 256];
        float4 a3 = r3[t], b3 = r3[t + 256];
        acc0.x += a0.x + a1.x + a2.x + a3.x;
        acc0.y += a0.y + a1.y + a2.y + a3.y;
        acc0.z += a0.z + a1.z + a2.z + a3.z;
        acc0.w += a0.w + a1.w + a2.w + a3.w;
        acc1.x += b0.x + b1.x + b2.x + b3.x;
        acc1.y += b0.y + b1.y + b2.y + b3.y;
        acc1.z += b0.z + b1.z + b2.z + b3.z;
        acc1.w += b0.w + b1.w + b2.w + b3.w;
    }
    for (; tk < nt; tk++) {
        const float4* r0 = (const float4*)(emb + (size_t)toks[tk] * D);
        float4 a = r0[t], bb = r0[t + 256];
        acc0.x += a.x; acc0.y += a.y; acc0.z += a.z; acc0.w += a.w;
        acc1.x += bb.x; acc1.y += bb.y; acc1.z += bb.z; acc1.w += bb.w;
    }

    float4* out = (float4*)(g_psum + ((size_t)h * B * P + b * P + p) * D);
    out[t]       = acc0;
    out[t + 256] = acc1;
}

// ---------------- final: score[b,p] = (sum_q psum_q . v[b]) / len + c[b], masked --------
__global__ void k_dot(const int* __restrict__ plen, float* __restrict__ out) {
    const int bp = blockIdx.x;            // 512 blocks
    const int b = bp >> 4, p = bp & 15;
    const int t = threadIdx.x;

    const float4* v4 = (const float4*)(g_v + (size_t)b * D);
    float s = 0.0f;
    #pragma unroll
    for (int i = 0; i < 2; i++) {
        int d4 = t + i * 256;              // over 512 float4
        float4 vv = v4[d4];
        float4 acc = make_float4(0.f, 0.f, 0.f, 0.f);
        #pragma unroll
        for (int q = 0; q < NQ; q++) {
            const float4* s4 = (const float4*)(g_psum + ((size_t)q * B * P + b * P + p) * D);
            float4 x = s4[d4];
            acc.x += x.x; acc.y += x.y; acc.z += x.z; acc.w += x.w;
        }
        s += acc.x * vv.x + acc.y * vv.y + acc.z * vv.z + acc.w * vv.w;
    }
    __shared__ float red[256];
    red[t] = s;
    __syncthreads();
    for (int o = 128; o; o >>= 1) {
        if (t < o) red[t] += red[t + o];
        __syncthreads();
    }
    if (t == 0) {
        int len = plen[b * P + p];
        float denom = (float)(len > 0 ? len : 1);
        out[bp] = (len > 0) ? (red[0] / denom + g_c[b]) : 0.0f;
    }
}

// ---------------- launch: fork-join; k_psum submitted 6th so ncu (-s 5 -c 1) captures it --
extern "C" void kernel_launch(void* const* d_in, const int* in_sizes, int n_in,
                              void* d_out, int out_size) {
    const int*   queries = (const int*)d_in[0];
    const int*   qlen    = (const int*)d_in[1];
    const int*   docs    = (const int*)d_in[2];
    const int*   plen    = (const int*)d_in[3];
    const float* emb     = (const float*)d_in[4];
    const float* W       = (const float*)d_in[5];
    const float* bias    = (const float*)d_in[6];
    float*       out     = (float*)d_out;

    float *qrep_p, *qenc_p, *v_p;
    cudaGetSymbolAddress((void**)&qrep_p, g_qrep);
    cudaGetSymbolAddress((void**)&qenc_p, g_qenc);
    cudaGetSymbolAddress((void**)&v_p, g_v);

    cudaStream_t s2;
    cudaStreamCreateWithFlags(&s2, cudaStreamNonBlocking);
    cudaEvent_t ef, ej;
    cudaEventCreateWithFlags(&ef, cudaEventDisableTiming);
    cudaEventCreateWithFlags(&ej, cudaEventDisableTiming);

    // fork point: s2 may start as soon as the stream-0 work prior to this point is done
    cudaEventRecord(ef, 0);
    cudaStreamWaitEvent(s2, ef, 0);

    // chain on stream 0 (launches 1-5)
    k_qrep<<<dim3(B, 8), 256>>>(queries, qlen, emb);
    k_gemm<<<dim3(2048 / TILE_N, KSPLIT), 256>>>(qrep_p, W, 0);
    k_reduce<<<64, 256>>>(qenc_p, bias, 1);
    k_gemm<<<dim3(2048 / TILE_N, KSPLIT), 256>>>(qenc_p, W, 1);
    k_reduce<<<64, 256>>>(v_p, bias, 0);

    // gather on s2 (launch 6 in submission order -> ncu captures it; no dep on chain)
    k_psum<<<dim3(B, P, NQ), 256, 0, s2>>>(docs, plen, emb);

    k_qc<<<B, 256>>>(bias);

    // join
    cudaEventRecord(ej, s2);
    cudaStreamWaitEvent(0, ej, 0);
    k_dot<<<B * P, 256>>>(plen, out);
}

// round 4
// speedup vs baseline: 1.0603x; 1.0603x over previous
#include <cuda_runtime.h>
#include <cuda_bf16.h>

// Problem constants
#define B    32
#define LQ   32
#define DLEN 4096
#define P    16
#define D    2048
#define H    2048
#define V    50257

#define KSPLIT 16           // k-split for skinny GEMMs
#define TILE_N 64
#define KB     64
#define NQ     2            // halves per passage in psum
#define NPASS  4            // vocab-range passes for L2 locality

// ---------------- scratch (device globals; no allocation allowed) ----------------
__device__ float g_qrep[B * D];
__device__ float g_qenc[B * H];
__device__ float g_v[B * D];
__device__ float g_part[KSPLIT * B * 2048];      // GEMM partials (4 MB)
__device__ float g_c[B];
__device__ float g_psum[NQ * B * P * D];         // passage embedding sums (8 MB)

// ---------------- q_rep = masked mean of query token embeddings ----------------
__global__ void k_qrep(const int* __restrict__ queries,
                       const int* __restrict__ qlen,
                       const float* __restrict__ emb) {
    int b = blockIdx.x;
    __shared__ int toks[LQ];
    if (threadIdx.x < LQ) toks[threadIdx.x] = queries[b * LQ + threadIdx.x];
    int len = qlen[b];
    __syncthreads();
    float inv = 1.0f / (float)len;
    int d = blockIdx.y * 256 + threadIdx.x;
    float s = 0.0f;
    for (int l = 0; l < len; l++) s += emb[(size_t)toks[l] * D + d];
    g_qrep[b * D + d] = s * inv;
}

// ---------------- skinny GEMM  C[32,2048] = A[32,2048] x W (optionally transposed) ----
__global__ void k_gemm(const float* __restrict__ A,
                       const float* __restrict__ W,
                       int transW) {
    const int n0 = blockIdx.x * TILE_N;
    const int k0 = blockIdx.y * (2048 / KSPLIT);
    __shared__ float As[32][KB];
    __shared__ float Ws[TILE_N][KB + 1];

    const int t  = threadIdx.x;      // 256 threads
    const int tb = t >> 5;
    const int tn = t & 31;

    float acc00 = 0.f, acc01 = 0.f, acc10 = 0.f, acc11 = 0.f;
    float acc20 = 0.f, acc21 = 0.f, acc30 = 0.f, acc31 = 0.f;

    for (int kc = 0; kc < (2048 / KSPLIT); kc += KB) {
        const int kbase = k0 + kc;
        #pragma unroll
        for (int i = 0; i < 8; i++) {
            int flat = t + i * 256;
            int bb = flat >> 6, kk = flat & 63;
            As[bb][kk] = A[bb * 2048 + kbase + kk];
        }
        if (!transW) {
            #pragma unroll
            for (int i = 0; i < 16; i++) {
                int flat = t + i * 256;
                int nn = flat >> 6, kk = flat & 63;
                Ws[nn][kk] = W[(size_t)(n0 + nn) * 2048 + kbase + kk];
            }
        } else {
            #pragma unroll
            for (int i = 0; i < 16; i++) {
                int flat = t + i * 256;
                int nn = flat & 63, kk = flat >> 6;
                Ws[nn][kk] = W[(size_t)(kbase + kk) * 2048 + n0 + nn];
            }
        }
        __syncthreads();

        #pragma unroll 16
        for (int k = 0; k < KB; k++) {
            float a0 = As[tb * 4 + 0][k];
            float a1 = As[tb * 4 + 1][k];
            float a2 = As[tb * 4 + 2][k];
            float a3 = As[tb * 4 + 3][k];
            float w0 = Ws[tn][k];
            float w1 = Ws[tn + 32][k];
            acc00 += a0 * w0; acc01 += a0 * w1;
            acc10 += a1 * w0; acc11 += a1 * w1;
            acc20 += a2 * w0; acc21 += a2 * w1;
            acc30 += a3 * w0; acc31 += a3 * w1;
        }
        __syncthreads();
    }

    float* out = g_part + (size_t)blockIdx.y * 32 * 2048;
    out[(tb * 4 + 0) * 2048 + n0 + tn]      = acc00;
    out[(tb * 4 + 0) * 2048 + n0 + tn + 32] = acc01;
    out[(tb * 4 + 1) * 2048 + n0 + tn]      = acc10;
    out[(tb * 4 + 1) * 2048 + n0 + tn + 32] = acc11;
    out[(tb * 4 + 2) * 2048 + n0 + tn]      = acc20;
    out[(tb * 4 + 2) * 2048 + n0 + tn + 32] = acc21;
    out[(tb * 4 + 3) * 2048 + n0 + tn]      = acc30;
    out[(tb * 4 + 3) * 2048 + n0 + tn + 32] = acc31;
}

// vectorized partial reduce over 16384 float4
__global__ void k_reduce(float* __restrict__ C,
                         const float* __restrict__ bias,
                         int addBias) {
    int idx = blockIdx.x * 256 + threadIdx.x;
    const float4* part4 = (const float4*)g_part;
    float4 s = make_float4(0.f, 0.f, 0.f, 0.f);
    #pragma unroll
    for (int sp = 0; sp < KSPLIT; sp++) {
        float4 x = part4[sp * 16384 + idx];
        s.x += x.x; s.y += x.y; s.z += x.z; s.w += x.w;
    }
    if (addBias) {
        float4 bb = ((const float4*)bias)[idx & 511];
        s.x += bb.x; s.y += bb.y; s.z += bb.z; s.w += bb.w;
    }
    ((float4*)C)[idx] = s;
}

// c[b] = q_enc[b] . bias
__global__ void k_qc(const float* __restrict__ bias) {
    int b = blockIdx.x;
    float s = 0.0f;
    for (int i = threadIdx.x; i < H; i += 256) s += g_qenc[b * H + i] * bias[i];
    __shared__ float red[256];
    red[threadIdx.x] = s;
    __syncthreads();
    for (int o = 128; o; o >>= 1) {
        if (threadIdx.x < o) red[threadIdx.x] += red[threadIdx.x + o];
        __syncthreads();
    }
    if (threadIdx.x == 0) g_c[b] = red[0];
}

// ---------------- passage embedding sums: vocab-range multi-pass for L2 reuse --------
// grid (B, P, NQ); block sums its half-passage's emb rows into [D] accumulator,
// processing tokens in NPASS vocab-id windows so concurrent blocks share an
// L2-resident slice of emb. Per-block summation order is fixed -> deterministic.
__global__ void k_psum(const int* __restrict__ docs,
                       const int* __restrict__ plen,
                       const float* __restrict__ emb) {
    const int b = blockIdx.x, p = blockIdx.y, h = blockIdx.z;
    const int t = threadIdx.x;

    __shared__ int toks[130];
    __shared__ int mt[130];
    __shared__ int info[2];
    __shared__ int nmatch;

    if (t == 0) {
        int start = 0;
        for (int q = 0; q < p; q++) start += plen[b * P + q];
        int len = plen[b * P + p];
        int h0 = (len + 1) >> 1;
        info[0] = start + (h ? h0 : 0);
        info[1] = h ? (len - h0) : h0;
    }
    __syncthreads();
    const int hstart = info[0];
    const int nt = info[1];
    if (t < nt) toks[t] = docs[b * DLEN + hstart + t];
    __syncthreads();

    float4 acc0 = make_float4(0.f, 0.f, 0.f, 0.f);
    float4 acc1 = make_float4(0.f, 0.f, 0.f, 0.f);

    const int R = (V + NPASS - 1) / NPASS;   // vocab window width

    for (int pass = 0; pass < NPASS; pass++) {
        const int lo = pass * R;
        const int hi = lo + R;
        if (t == 0) {
            int c = 0;
            for (int i = 0; i < nt; i++) {
                int id = toks[i];
                if (id >= lo && id < hi) mt[c++] = id;
            }
            nmatch = c;
        }
        __syncthreads();
        const int nm = nmatch;

        int tk = 0;
        for (; tk + 4 <= nm; tk += 4) {
            const float4* r0 = (const float4*)(emb + (size_t)mt[tk + 0] * D);
            const float4* r1 = (const float4*)(emb + (size_t)mt[tk + 1] * D);
            const float4* r2 = (const float4*)(emb + (size_t)mt[tk + 2] * D);
            const float4* r3 = (const float4*)(emb + (size_t)mt[tk + 3] * D);
            float4 a0 = r0[t], b0 = r0[t + 256];
            float4 a1 = r1[t], b1 = r1[t + 256];
            float4 a2 = r2[t], b2 = r2[t + 256];
            float4 a3 = r3[t], b3 = r3[t + 256];
            acc0.x += a0.x + a1.x + a2.x + a3.x;
            acc0.y += a0.y + a1.y + a2.y + a3.y;
            acc0.z += a0.z + a1.z + a2.z + a3.z;
            acc0.w += a0.w + a1.w + a2.w + a3.w;
            acc1.x += b0.x + b1.x + b2.x + b3.x;
            acc1.y += b0.y + b1.y + b2.y + b3.y;
            acc1.z += b0.z + b1.z + b2.z + b3.z;
            acc1.w += b0.w + b1.w + b2.w + b3.w;
        }
        for (; tk < nm; tk++) {
            const float4* r0 = (const float4*)(emb + (size_t)mt[tk] * D);
            float4 a = r0[t], bb = r0[t + 256];
            acc0.x += a.x; acc0.y += a.y; acc0.z += a.z; acc0.w += a.w;
            acc1.x += bb.x; acc1.y += bb.y; acc1.z += bb.z; acc1.w += bb.w;
        }
        __syncthreads();
    }

    float4* out = (float4*)(g_psum + ((size_t)h * B * P + b * P + p) * D);
    out[t]       = acc0;
    out[t + 256] = acc1;
}

// ---------------- final: score[b,p] = (sum_h psum_h . v[b]) / len + c[b], masked ------
__global__ void k_dot(const int* __restrict__ plen, float* __restrict__ out) {
    const int bp = blockIdx.x;            // 512 blocks
    const int b = bp >> 4, p = bp & 15;
    const int t = threadIdx.x;

    const float4* v4 = (const float4*)(g_v + (size_t)b * D);
    float s = 0.0f;
    #pragma unroll
    for (int i = 0; i < 2; i++) {
        int d4 = t + i * 256;
        float4 vv = v4[d4];
        float4 acc = make_float4(0.f, 0.f, 0.f, 0.f);
        #pragma unroll
        for (int q = 0; q < NQ; q++) {
            const float4* s4 = (const float4*)(g_psum + ((size_t)q * B * P + b * P + p) * D);
            float4 x = s4[d4];
            acc.x += x.x; acc.y += x.y; acc.z += x.z; acc.w += x.w;
        }
        s += acc.x * vv.x + acc.y * vv.y + acc.z * vv.z + acc.w * vv.w;
    }
    __shared__ float red[256];
    red[t] = s;
    __syncthreads();
    for (int o = 128; o; o >>= 1) {
        if (t < o) red[t] += red[t + o];
        __syncthreads();
    }
    if (t == 0) {
        int len = plen[b * P + p];
        float denom = (float)(len > 0 ? len : 1);
        out[bp] = (len > 0) ? (red[0] / denom + g_c[b]) : 0.0f;
    }
}

// ---------------- launch: psum submitted FIRST (critical path), chain overlaps ---------
extern "C" void kernel_launch(void* const* d_in, const int* in_sizes, int n_in,
                              void* d_out, int out_size) {
    const int*   queries = (const int*)d_in[0];
    const int*   qlen    = (const int*)d_in[1];
    const int*   docs    = (const int*)d_in[2];
    const int*   plen    = (const int*)d_in[3];
    const float* emb     = (const float*)d_in[4];
    const float* W       = (const float*)d_in[5];
    const float* bias    = (const float*)d_in[6];
    float*       out     = (float*)d_out;

    float *qrep_p, *qenc_p, *v_p;
    cudaGetSymbolAddress((void**)&qrep_p, g_qrep);
    cudaGetSymbolAddress((void**)&qenc_p, g_qenc);
    cudaGetSymbolAddress((void**)&v_p, g_v);

    cudaStream_t s2;
    cudaStreamCreateWithFlags(&s2, cudaStreamNonBlocking);
    cudaEvent_t ef, ej;
    cudaEventCreateWithFlags(&ef, cudaEventDisableTiming);
    cudaEventCreateWithFlags(&ej, cudaEventDisableTiming);

    // fork: gather starts immediately on s2, concurrently with the GEMM chain
    cudaEventRecord(ef, 0);
    cudaStreamWaitEvent(s2, ef, 0);
    k_psum<<<dim3(B, P, NQ), 256, 0, s2>>>(docs, plen, emb);

    k_qrep<<<dim3(B, 8), 256>>>(queries, qlen, emb);
    k_gemm<<<dim3(2048 / TILE_N, KSPLIT), 256>>>(qrep_p, W, 0);
    k_reduce<<<64, 256>>>(qenc_p, bias, 1);
    k_gemm<<<dim3(2048 / TILE_N, KSPLIT), 256>>>(qenc_p, W, 1);
    k_reduce<<<64, 256>>>(v_p, bias, 0);
    k_qc<<<B, 256>>>(bias);

    // join
    cudaEventRecord(ej, s2);
    cudaStreamWaitEvent(0, ej, 0);
    k_dot<<<B * P, 256>>>(plen, out);
}